// round 1
// baseline (speedup 1.0000x reference)
#include <cuda_runtime.h>
#include <math.h>

// ---------------- problem constants (fixed-shape benchmark) ----------------
#define T_TOKENS 4096
#define H_DIM    2048
#define F_DIM    7168
#define N_EXP    8
#define NPAIRS   (T_TOKENS * 2)     // top-2: 8192 (token, expert) pairs
#define BM       128
#define BK       16
#define BN       64
#define MAX_RT   (NPAIRS / BM + N_EXP)   // 72 worst-case row tiles

// ---------------- device scratch (static: no allocations allowed) ----------
__device__ __align__(16) float g_h[(size_t)NPAIRS * F_DIM];   // SwiGLU activations
__device__ __align__(16) float g_y[(size_t)NPAIRS * H_DIM];   // per-pair outputs (weighted)
__device__ int   g_gtoken[NPAIRS];     // grouped-by-expert token index
__device__ float g_gweight[NPAIRS];    // grouped routing weight
__device__ int   g_pairrow[NPAIRS];    // [t*2+k] -> grouped row index
__device__ int   g_sel[NPAIRS];        // [t*2+k] -> expert id
__device__ float g_wt[NPAIRS];         // [t*2+k] -> normalized weight
__device__ int   g_counts[N_EXP];
__device__ int   g_cursor[N_EXP];
__device__ int   g_offsets[N_EXP + 1];
__device__ int   g_tile_e[MAX_RT];
__device__ int   g_tile_r[MAX_RT];
__device__ int   g_ntiles;

// ---------------------------------------------------------------------------
__global__ void init_kernel() {
    if (threadIdx.x < N_EXP) g_counts[threadIdx.x] = 0;
}

// One block per token: logits = x[t] . gate_w[e], softmax-top2 weights.
__global__ void router_kernel(const float* __restrict__ x,
                              const float* __restrict__ gw,
                              float* __restrict__ logits_out) {
    const int t   = blockIdx.x;
    const int tid = threadIdx.x;

    float acc[N_EXP];
#pragma unroll
    for (int e = 0; e < N_EXP; e++) acc[e] = 0.0f;

    const float4* xr = (const float4*)(x + (size_t)t * H_DIM);
#pragma unroll 2
    for (int i = tid; i < H_DIM / 4; i += 256) {
        float4 xv = xr[i];
#pragma unroll
        for (int e = 0; e < N_EXP; e++) {
            float4 gv = ((const float4*)(gw + (size_t)e * H_DIM))[i];
            acc[e] += xv.x * gv.x + xv.y * gv.y + xv.z * gv.z + xv.w * gv.w;
        }
    }
    // warp reduce
#pragma unroll
    for (int e = 0; e < N_EXP; e++)
#pragma unroll
        for (int off = 16; off > 0; off >>= 1)
            acc[e] += __shfl_down_sync(0xffffffffu, acc[e], off);

    __shared__ float sred[N_EXP][8];
    __shared__ float slog[N_EXP];
    const int w = tid >> 5, lane = tid & 31;
    if (lane == 0) {
#pragma unroll
        for (int e = 0; e < N_EXP; e++) sred[e][w] = acc[e];
    }
    __syncthreads();
    if (tid < N_EXP) {
        float s = 0.0f;
#pragma unroll
        for (int ww = 0; ww < 8; ww++) s += sred[tid][ww];
        slog[tid] = s;
        if (logits_out) logits_out[(size_t)t * N_EXP + tid] = s;
    }
    __syncthreads();
    if (tid == 0) {
        int i0 = 0; float v0 = slog[0];
#pragma unroll
        for (int e = 1; e < N_EXP; e++) { if (slog[e] > v0) { v0 = slog[e]; i0 = e; } }
        int i1 = -1; float v1 = -1e30f;
#pragma unroll
        for (int e = 0; e < N_EXP; e++) {
            if (e == i0) continue;
            if (slog[e] > v1) { v1 = slog[e]; i1 = e; }
        }
        // normalized top-2 softmax weights: w0 = p0/(p0+p1)
        float w0 = 1.0f / (1.0f + expf(v1 - v0));
        float w1 = 1.0f - w0;
        g_sel[2 * t]     = i0;  g_sel[2 * t + 1] = i1;
        g_wt[2 * t]      = w0;  g_wt[2 * t + 1]  = w1;
        atomicAdd(&g_counts[i0], 1);
        atomicAdd(&g_counts[i1], 1);
    }
}

// Single thread: offsets + row-tile table (tiny: 8 experts, <=72 tiles).
__global__ void scan_kernel() {
    int off = 0, nt = 0;
    for (int e = 0; e < N_EXP; e++) {
        g_offsets[e] = off;
        g_cursor[e]  = off;
        int c = g_counts[e];
        int ntile = (c + BM - 1) / BM;
        for (int i = 0; i < ntile; i++) { g_tile_e[nt] = e; g_tile_r[nt] = i * BM; nt++; }
        off += c;
    }
    g_offsets[N_EXP] = off;
    g_ntiles = nt;
}

__global__ void scatter_kernel() {
    int t = blockIdx.x * blockDim.x + threadIdx.x;
    if (t >= T_TOKENS) return;
#pragma unroll
    for (int k = 0; k < 2; k++) {
        int e   = g_sel[2 * t + k];
        int idx = atomicAdd(&g_cursor[e], 1);
        g_gtoken[idx]      = t;
        g_gweight[idx]     = g_wt[2 * t + k];
        g_pairrow[2 * t + k] = idx;
    }
}

// ---------------- GEMM1: h = silu(X w1^T) * (X w3^T), grouped by expert -----
__global__ void __launch_bounds__(256)
gemm1_kernel(const float* __restrict__ x,
             const float* __restrict__ w1,
             const float* __restrict__ w3) {
    const int rt = blockIdx.y;
    if (rt >= g_ntiles) return;
    const int e        = g_tile_e[rt];
    const int row_base = g_offsets[e] + g_tile_r[rt];
    const int n_valid  = g_offsets[e + 1] - row_base;
    const int f0       = blockIdx.x * BN;
    const int tid      = threadIdx.x;

    __shared__ __align__(16) float As [BK][BM];
    __shared__ __align__(16) float Bs1[BK][BN];
    __shared__ __align__(16) float Bs3[BK][BN];

    const int la_r = tid >> 2;          // 0..63
    const int la_k = (tid & 3) * 4;     // 0,4,8,12
    const int r0c  = min(row_base + la_r,      NPAIRS - 1);
    const int r1c  = min(row_base + la_r + 64, NPAIRS - 1);
    const float* a0p = x  + (size_t)g_gtoken[r0c] * H_DIM + la_k;
    const float* a1p = x  + (size_t)g_gtoken[r1c] * H_DIM + la_k;
    const float* b1p = w1 + ((size_t)e * F_DIM + f0 + la_r) * H_DIM + la_k;
    const float* b3p = w3 + ((size_t)e * F_DIM + f0 + la_r) * H_DIM + la_k;

    const int ty = tid >> 4, tx = tid & 15;

    float acc1[8][4], acc3[8][4];
#pragma unroll
    for (int i = 0; i < 8; i++)
#pragma unroll
        for (int j = 0; j < 4; j++) { acc1[i][j] = 0.0f; acc3[i][j] = 0.0f; }

    for (int k0 = 0; k0 < H_DIM; k0 += BK) {
        float4 av0 = *(const float4*)(a0p + k0);
        float4 av1 = *(const float4*)(a1p + k0);
        float4 bv1 = *(const float4*)(b1p + k0);
        float4 bv3 = *(const float4*)(b3p + k0);
        __syncthreads();
        As[la_k + 0][la_r] = av0.x; As[la_k + 1][la_r] = av0.y;
        As[la_k + 2][la_r] = av0.z; As[la_k + 3][la_r] = av0.w;
        As[la_k + 0][la_r + 64] = av1.x; As[la_k + 1][la_r + 64] = av1.y;
        As[la_k + 2][la_r + 64] = av1.z; As[la_k + 3][la_r + 64] = av1.w;
        Bs1[la_k + 0][la_r] = bv1.x; Bs1[la_k + 1][la_r] = bv1.y;
        Bs1[la_k + 2][la_r] = bv1.z; Bs1[la_k + 3][la_r] = bv1.w;
        Bs3[la_k + 0][la_r] = bv3.x; Bs3[la_k + 1][la_r] = bv3.y;
        Bs3[la_k + 2][la_r] = bv3.z; Bs3[la_k + 3][la_r] = bv3.w;
        __syncthreads();
#pragma unroll
        for (int k = 0; k < BK; k++) {
            float4 a04 = *(const float4*)&As[k][ty * 8];
            float4 a14 = *(const float4*)&As[k][ty * 8 + 4];
            float4 b1v = *(const float4*)&Bs1[k][tx * 4];
            float4 b3v = *(const float4*)&Bs3[k][tx * 4];
            float a[8] = {a04.x, a04.y, a04.z, a04.w, a14.x, a14.y, a14.z, a14.w};
            float b1a[4] = {b1v.x, b1v.y, b1v.z, b1v.w};
            float b3a[4] = {b3v.x, b3v.y, b3v.z, b3v.w};
#pragma unroll
            for (int i = 0; i < 8; i++)
#pragma unroll
                for (int j = 0; j < 4; j++) {
                    acc1[i][j] += a[i] * b1a[j];
                    acc3[i][j] += a[i] * b3a[j];
                }
        }
    }
#pragma unroll
    for (int i = 0; i < 8; i++) {
        int r = ty * 8 + i;
        if (r < n_valid) {
            float4 hv;
            float s;
            s = acc1[i][0]; hv.x = s * (1.0f / (1.0f + expf(-s))) * acc3[i][0];
            s = acc1[i][1]; hv.y = s * (1.0f / (1.0f + expf(-s))) * acc3[i][1];
            s = acc1[i][2]; hv.z = s * (1.0f / (1.0f + expf(-s))) * acc3[i][2];
            s = acc1[i][3]; hv.w = s * (1.0f / (1.0f + expf(-s))) * acc3[i][3];
            *(float4*)&g_h[(size_t)(row_base + r) * F_DIM + f0 + tx * 4] = hv;
        }
    }
}

// ---------------- GEMM2: y = (h w2^T) * route_weight -----------------------
__global__ void __launch_bounds__(256)
gemm2_kernel(const float* __restrict__ w2) {
    const int rt = blockIdx.y;
    if (rt >= g_ntiles) return;
    const int e        = g_tile_e[rt];
    const int row_base = g_offsets[e] + g_tile_r[rt];
    const int n_valid  = g_offsets[e + 1] - row_base;
    const int h0       = blockIdx.x * BN;
    const int tid      = threadIdx.x;

    __shared__ __align__(16) float As[BK][BM];
    __shared__ __align__(16) float Bs[BK][BN];

    const int la_r = tid >> 2;
    const int la_k = (tid & 3) * 4;
    const int r0c  = min(row_base + la_r,      NPAIRS - 1);
    const int r1c  = min(row_base + la_r + 64, NPAIRS - 1);
    const float* a0p = g_h + (size_t)r0c * F_DIM + la_k;
    const float* a1p = g_h + (size_t)r1c * F_DIM + la_k;
    const float* bp  = w2  + ((size_t)e * H_DIM + h0 + la_r) * F_DIM + la_k;

    const int ty = tid >> 4, tx = tid & 15;

    float acc[8][4];
#pragma unroll
    for (int i = 0; i < 8; i++)
#pragma unroll
        for (int j = 0; j < 4; j++) acc[i][j] = 0.0f;

    for (int k0 = 0; k0 < F_DIM; k0 += BK) {
        float4 av0 = *(const float4*)(a0p + k0);
        float4 av1 = *(const float4*)(a1p + k0);
        float4 bv  = *(const float4*)(bp + k0);
        __syncthreads();
        As[la_k + 0][la_r] = av0.x; As[la_k + 1][la_r] = av0.y;
        As[la_k + 2][la_r] = av0.z; As[la_k + 3][la_r] = av0.w;
        As[la_k + 0][la_r + 64] = av1.x; As[la_k + 1][la_r + 64] = av1.y;
        As[la_k + 2][la_r + 64] = av1.z; As[la_k + 3][la_r + 64] = av1.w;
        Bs[la_k + 0][la_r] = bv.x; Bs[la_k + 1][la_r] = bv.y;
        Bs[la_k + 2][la_r] = bv.z; Bs[la_k + 3][la_r] = bv.w;
        __syncthreads();
#pragma unroll
        for (int k = 0; k < BK; k++) {
            float4 a04 = *(const float4*)&As[k][ty * 8];
            float4 a14 = *(const float4*)&As[k][ty * 8 + 4];
            float4 bv4 = *(const float4*)&Bs[k][tx * 4];
            float a[8] = {a04.x, a04.y, a04.z, a04.w, a14.x, a14.y, a14.z, a14.w};
            float b[4] = {bv4.x, bv4.y, bv4.z, bv4.w};
#pragma unroll
            for (int i = 0; i < 8; i++)
#pragma unroll
                for (int j = 0; j < 4; j++) acc[i][j] += a[i] * b[j];
        }
    }
#pragma unroll
    for (int i = 0; i < 8; i++) {
        int r = ty * 8 + i;
        if (r < n_valid) {
            float wgt = g_gweight[row_base + r];
            float4 yv;
            yv.x = acc[i][0] * wgt; yv.y = acc[i][1] * wgt;
            yv.z = acc[i][2] * wgt; yv.w = acc[i][3] * wgt;
            *(float4*)&g_y[(size_t)(row_base + r) * H_DIM + h0 + tx * 4] = yv;
        }
    }
}

// ---------------- combine: out[t] = y[slot(t,0)] + y[slot(t,1)] ------------
__global__ void combine_kernel(float* __restrict__ out) {
    int idx = blockIdx.x * blockDim.x + threadIdx.x;     // over T*H/4
    int t = idx / (H_DIM / 4);
    int c = idx % (H_DIM / 4);
    int p0 = g_pairrow[2 * t];
    int p1 = g_pairrow[2 * t + 1];
    float4 y0 = *(const float4*)&g_y[(size_t)p0 * H_DIM + c * 4];
    float4 y1 = *(const float4*)&g_y[(size_t)p1 * H_DIM + c * 4];
    float4 o;
    o.x = y0.x + y1.x; o.y = y0.y + y1.y;
    o.z = y0.z + y1.z; o.w = y0.w + y1.w;
    ((float4*)out)[idx] = o;
}

// ---------------------------------------------------------------------------
extern "C" void kernel_launch(void* const* d_in, const int* in_sizes, int n_in,
                              void* d_out, int out_size) {
    const float* x  = (const float*)d_in[0];   // hidden_states [B,S,H]
    const float* gw = (const float*)d_in[1];   // gate_w [E,H]
    const float* w1 = (const float*)d_in[2];   // w1 [E,F,H]
    const float* w2 = (const float*)d_in[3];   // w2 [E,H,F]
    const float* w3 = (const float*)d_in[4];   // w3 [E,F,H]
    float* out = (float*)d_out;
    // output = flatten(out) ++ flatten(router_logits) if room
    float* logits = nullptr;
    if (out_size >= T_TOKENS * H_DIM + T_TOKENS * N_EXP)
        logits = out + (size_t)T_TOKENS * H_DIM;

    init_kernel<<<1, 32>>>();
    router_kernel<<<T_TOKENS, 256>>>(x, gw, logits);
    scan_kernel<<<1, 1>>>();
    scatter_kernel<<<(T_TOKENS + 255) / 256, 256>>>();

    dim3 g1(F_DIM / BN, MAX_RT);
    gemm1_kernel<<<g1, 256>>>(x, w1, w3);
    dim3 g2(H_DIM / BN, MAX_RT);
    gemm2_kernel<<<g2, 256>>>(w2);

    combine_kernel<<<(T_TOKENS * (H_DIM / 4)) / 256, 256>>>(out);
}